// round 12
// baseline (speedup 1.0000x reference)
#include <cuda_runtime.h>
#include <cuda_fp16.h>

#define HH 128
#define WW 256
#define SS 12
#define CC 32
#define BAND 74
#define HW (HH * WW)
#define WP 264
#define HP 130
#define PLANE (HP * WP)
#define NBLK 512

// Band pair table, fp16 with baked scale (C = 7/32*log2(e)); 4B access only.
__device__ __half2 g_band2h[HH * BAND * WW];     // 9.7 MB
__device__ float g_noiseA[SS * PLANE];
__device__ float g_noiseB[SS * PLANE];
__device__ float2 g_mdsv[HW];

// Grid barrier state (zero-init; gen monotonic across graph replays).
__device__ unsigned g_cnt[3];
__device__ volatile unsigned g_gen[3];

#define FMA2(d, a, b, c) \
    asm("fma.rn.f32x2 %0, %1, %2, %3;" : "=l"(d) : "l"(a), "l"(b), "l"(c))
#define PACK2(out, v) \
    asm("mov.b64 %0, {%1, %1};" : "=l"(out) : "r"(__float_as_uint(v)))
#define UNPACK2(lo, hi, in) \
    asm("mov.b64 {%0, %1}, %2;" : "=r"(lo), "=r"(hi) : "l"(in))

__device__ __forceinline__ float ex2(float x) {
    float r; asm("ex2.approx.f32 %0, %1;" : "=f"(r) : "f"(x)); return r;
}
__device__ __forceinline__ float rcp(float x) {
    float r; asm("rcp.approx.f32 %0, %1;" : "=f"(r) : "f"(x)); return r;
}

// ---------------------------------------------------------------------------
// Front kernel (unchanged, known good): band GEMM + prep.
// ---------------------------------------------------------------------------
__global__ __launch_bounds__(192) void front_kernel(
    const float* __restrict__ left, const float* __restrict__ right,
    const float* __restrict__ minD, const float* __restrict__ maxD,
    const float* __restrict__ noise) {
    const int h = blockIdx.y;
    const int tid = threadIdx.x;

    if (blockIdx.x == 2) {
        for (int i = tid; i < SS * WW; i += 192) {
            int s = i >> 8, w = i & 255;
            g_noiseA[s * PLANE + (h + 1) * WP + w + 1] = noise[s * HW + h * WW + w];
        }
        for (int w = tid; w < WW; w += 192) {
            int pix = h * WW + w;
            float md = fmaxf(minD[pix], 0.0f);
            float Md = fmaxf(maxD[pix], 0.0f);
            g_mdsv[pix] = make_float2(md, (Md - md) * (1.0f / (float)(SS + 1)));
        }
        return;
    }

    __shared__ float pool[12288];
    float (*As)[128] = (float(*)[128])pool;
    float (*Rs)[WW]  = (float(*)[WW])(pool + 4096);
    float (*Sb)[129] = (float(*)[129])pool;

    const int wbase = blockIdx.x * 128;

    for (int i = tid; i < CC * 128; i += 192) {
        int c = i >> 7, wl = i & 127;
        As[c][wl] = left[(c * HH + h) * WW + wbase + wl];
    }
    for (int i = tid; i < CC * WW; i += 192) {
        int c = i >> 8, x = i & 255;
        Rs[c][x] = right[(c * HH + h) * WW + x];
    }
    __syncthreads();

    const int tw = tid / 12;
    const int j  = tid % 12;
    const int twg = (wbase >> 3) + tw;
    const int txg = twg - 9 + j;
    const bool active = (j < 11) && (txg >= 0) && (txg <= 31);

    const int wl = tw * 8;
    const int x  = txg * 8;

    unsigned long long acc2[8][4];
    #pragma unroll
    for (int i = 0; i < 8; i++)
        #pragma unroll
        for (int q = 0; q < 4; q++) acc2[i][q] = 0ULL;

    if (active) {
        #pragma unroll 8
        for (int k = 0; k < CC; k++) {
            float a[8];
            *(float4*)&a[0] = *(const float4*)&As[k][wl];
            *(float4*)&a[4] = *(const float4*)&As[k][wl + 4];
            ulonglong2 t0 = *(const ulonglong2*)&Rs[k][x];
            ulonglong2 t1 = *(const ulonglong2*)&Rs[k][x + 4];
            unsigned long long b2[4] = {t0.x, t0.y, t1.x, t1.y};
            #pragma unroll
            for (int i = 0; i < 8; i++) {
                unsigned long long a2;
                PACK2(a2, a[i]);
                #pragma unroll
                for (int q = 0; q < 4; q++)
                    FMA2(acc2[i][q], a2, b2[q], acc2[i][q]);
            }
        }
    }
    __syncthreads();

    if (active) {
        const int xl = x - wbase;
        #pragma unroll
        for (int i = 0; i < 8; i++) {
            #pragma unroll
            for (int q = 0; q < 8; q++) {
                unsigned lo, hi;
                UNPACK2(lo, hi, acc2[i][q >> 1]);
                float v = __uint_as_float((q & 1) ? hi : lo);
                int b = wl + i + 1 - xl - q;
                if (b >= 0 && b <= 73) Sb[b][wl + i] = v;
            }
        }
    }
    __syncthreads();

    const float Cs = 0.21875f * 1.4426950408889634f;
    __half2* dst = g_band2h + h * BAND * WW + wbase;
    for (int i2 = tid; i2 < 73 * 128; i2 += 192) {
        int b = (i2 >> 7) + 1;
        int wli = i2 & 127;
        int x0 = wbase + wli + 1 - b;
        float v0 = (x0 >= 0) ? Cs * Sb[b][wli] : 0.0f;
        float v1 = (x0 >= -1 && x0 <= 254) ? Cs * Sb[b - 1][wli] : 0.0f;
        dst[b * WW + wli] = __floats2half2_rn(v0, v1);
    }
}

// ---------------------------------------------------------------------------
// Sense-reversing grid barrier; gen counters monotonic -> graph-replay safe.
// All NBLK blocks are guaranteed resident (512 blocks, 0 smem, <=42 regs).
// ---------------------------------------------------------------------------
__device__ __forceinline__ void grid_barrier(int j) {
    __syncthreads();
    if (threadIdx.x == 0 && threadIdx.y == 0) {
        __threadfence();
        unsigned mygen = g_gen[j];
        unsigned old = atomicAdd(&g_cnt[j], 1u);
        if (old == NBLK - 1) {
            g_cnt[j] = 0;
            __threadfence();
            g_gen[j] = mygen + 1;          // release
        } else {
            while (g_gen[j] == mygen) __nanosleep(64);
        }
        __threadfence();
    }
    __syncthreads();
}

// ---------------------------------------------------------------------------
// One pass body. Noise reads use __ldcg (L1-bypass: lines may be stale after
// other blocks rewrote them in a prior pass). Table reads use __ldg (read-only
// all kernel -> L1-warm for passes 1-3).
// ---------------------------------------------------------------------------
template<bool HORIZ, bool LAST>
__device__ __forceinline__ void do_pass(
    const float* __restrict__ nin, float* __restrict__ nout,
    float* __restrict__ disp_out,
    int pix, int pp0, int s0, float sv, float msx, float fw,
    const __half2* __restrict__ brow, int wp1) {

    float np[2][3];
    #pragma unroll
    for (int u = 0; u < 2; u++) {
        const int pp = pp0 + u * 6 * PLANE;
        np[u][1] = __ldcg(nin + pp);
        if (HORIZ) {
            np[u][0] = __ldcg(nin + pp - 1);
            np[u][2] = __ldcg(nin + pp + 1);
        } else {
            np[u][0] = __ldcg(nin + pp - WP);
            np[u][2] = __ldcg(nin + pp + WP);
        }
    }

    float xs[2][3], frac[2][3];
    __half2 dph[2][3];
    #pragma unroll
    for (int u = 0; u < 2; u++) {
        const float wim = fw - fmaf(sv, (float)(s0 + u * 6 + 1), msx);
        #pragma unroll
        for (int c = 0; c < 3; c++) {
            xs[u][c] = fmaf(np[u][c], -sv, wim);
            int k0 = __float2int_rd(xs[u][c]);
            frac[u][c] = xs[u][c] - (float)k0;
            int b0 = wp1 - k0;
            b0 = min(max(b0, 1), BAND - 1);
            dph[u][c] = __ldg(brow + b0 * WW);
        }
    }

    #pragma unroll
    for (int u = 0; u < 2; u++) {
        float e[3];
        #pragma unroll
        for (int c = 0; c < 3; c++) {
            float2 d = __half22float2(dph[u][c]);
            e[c] = ex2(fmaf(d.y - d.x, frac[u][c], d.x));
        }
        const float rZ = rcp(e[0] + e[1] + e[2]);
        const int s = s0 + u * 6;
        if (LAST) {
            float d = e[0] * (fw - xs[u][0]) + e[1] * (fw - xs[u][1])
                    + e[2] * (fw - xs[u][2]);
            disp_out[s * HW + pix] = d * rZ;
        } else {
            nout[pp0 + u * 6 * PLANE] =
                (e[0] * np[u][0] + e[1] * np[u][1] + e[2] * np[u][2]) * rZ;
        }
    }
}

// ---------------------------------------------------------------------------
// All 4 passes in one launch; table slice stays L1-resident across passes.
// grid (4, HH) = 512 blocks, block (64, 6).
// ---------------------------------------------------------------------------
__global__ __launch_bounds__(384, 4) void pm_all_kernel(float* __restrict__ disp_out) {
    const int w = blockIdx.x * 64 + threadIdx.x;
    const int h = blockIdx.y;
    const int s0 = threadIdx.y;
    const int pix = h * WW + w;
    const int pp0 = s0 * PLANE + (h + 1) * WP + (w + 1);

    const float2 ms = __ldg(&g_mdsv[pix]);
    const float sv = ms.y;
    const float fw = (float)w;
    const __half2* __restrict__ brow = g_band2h + h * (BAND * WW) + w;
    const int wp1 = w + 1;

    do_pass<true,  false>(g_noiseA, g_noiseB, disp_out, pix, pp0, s0, sv, ms.x, fw, brow, wp1);
    grid_barrier(0);
    do_pass<false, false>(g_noiseB, g_noiseA, disp_out, pix, pp0, s0, sv, ms.x, fw, brow, wp1);
    grid_barrier(1);
    do_pass<true,  false>(g_noiseA, g_noiseB, disp_out, pix, pp0, s0, sv, ms.x, fw, brow, wp1);
    grid_barrier(2);
    do_pass<false, true >(g_noiseB, g_noiseA, disp_out, pix, pp0, s0, sv, ms.x, fw, brow, wp1);
}

extern "C" void kernel_launch(void* const* d_in, const int* in_sizes, int n_in,
                              void* d_out, int out_size) {
    const float* left  = (const float*)d_in[0];
    const float* right = (const float*)d_in[1];
    const float* minD  = (const float*)d_in[2];
    const float* maxD  = (const float*)d_in[3];
    const float* noise = (const float*)d_in[4];
    float* disp = (float*)d_out;

    front_kernel<<<dim3(3, HH), 192>>>(left, right, minD, maxD, noise);
    pm_all_kernel<<<dim3(4, HH), dim3(64, 6)>>>(disp);
}